// round 1
// baseline (speedup 1.0000x reference)
#include <cuda_runtime.h>

// DMN_Encoder: 3-hop memory-network recurrence, B=128, N=2048, D=128.
// One persistent CTA per batch row; each hop is a single online-softmax pass
// over value[b] (1 MB), fusing s = (mask*v)·w_f, exp-weighting, and the
// o = P·features accumulation. u-update GEMV done per-CTA from L2-resident W.

#define B_ 128
#define N_ 2048
#define D_ 128
#define HOPS_ 3
#define NWARP 32            // 1024 threads
#define ROWS_PER_WARP (N_ / NWARP)   // 64

__global__ __launch_bounds__(1024, 1)
void dmn_encoder_kernel(const float* __restrict__ e1,
                        const float* __restrict__ value,
                        const float* __restrict__ mask,
                        const float* __restrict__ linw,
                        const float* __restrict__ linb,
                        const float* __restrict__ attw,
                        const float* __restrict__ attb,
                        float* __restrict__ out)
{
    const int b    = blockIdx.x;
    const int tid  = threadIdx.x;
    const int lane = tid & 31;
    const int warp = tid >> 5;

    __shared__ __align__(16) float u_s[D_];
    __shared__ __align__(16) float ub_s[D_];
    __shared__ __align__(16) float acc_s[NWARP][D_];
    __shared__ float l_s[NWARP];

    // w_f = attw[0:128], w_u = attw[128:256]; each lane owns 4 dims.
    const float4* attw4 = reinterpret_cast<const float4*>(attw);
    const float4 wf4 = attw4[lane];
    const float4 wu4 = attw4[32 + lane];
    const float  b0  = attb[0];

    if (tid < D_) u_s[tid] = e1[b * D_ + tid];
    __syncthreads();

    const float* vb = value + (size_t)b * N_ * D_;
    const float* mb = mask  + (size_t)b * N_;

    #pragma unroll 1
    for (int hop = 0; hop < HOPS_; hop++) {
        // ---- scalars from current u: c = u·w_u (redundant per warp, no sync) ----
        const float4 u4 = reinterpret_cast<const float4*>(u_s)[lane];
        float cp = u4.x*wu4.x + u4.y*wu4.y + u4.z*wu4.z + u4.w*wu4.w;
        #pragma unroll
        for (int o = 16; o; o >>= 1) cp += __shfl_xor_sync(0xffffffffu, cp, o);
        const float cb    = cp + b0;
        const float sigma = fmaxf(cb, 0.f);   // safe softmax shift (att >= 0)

        // ---- u_batch = relu(u @ W^T + bias): warp w computes rows 4w..4w+3 ----
        #pragma unroll
        for (int r = 0; r < 4; r++) {
            const int i = warp * 4 + r;
            const float4 w4 = reinterpret_cast<const float4*>(linw + (size_t)i * D_)[lane];
            float p = w4.x*u4.x + w4.y*u4.y + w4.z*u4.z + w4.w*u4.w;
            #pragma unroll
            for (int o = 16; o; o >>= 1) p += __shfl_xor_sync(0xffffffffu, p, o);
            if (lane == 0) ub_s[i] = fmaxf(p + linb[i], 0.f);
        }

        // ---- single streaming pass: att -> exp weight -> o accumulation ----
        float a0 = 0.f, a1 = 0.f, a2 = 0.f, a3 = 0.f, l = 0.f;
        const int n0 = warp * ROWS_PER_WARP;
        #pragma unroll 4
        for (int k = 0; k < ROWS_PER_WARP; k++) {
            const int n = n0 + k;
            const float4 v4 = reinterpret_cast<const float4*>(vb + (size_t)n * D_)[lane];
            const float  mk = __ldg(mb + n);
            float s = v4.x*wf4.x + v4.y*wf4.y + v4.z*wf4.z + v4.w*wf4.w;
            #pragma unroll
            for (int o = 16; o; o >>= 1) s += __shfl_xor_sync(0xffffffffu, s, o);
            float att = fmaxf(fmaf(s, mk, cb), 0.f);       // relu(mask*s + c + b0)
            float w   = __expf(fminf(att - sigma, 80.f)) * mk;
            l += w;
            a0 = fmaf(w, v4.x, a0);
            a1 = fmaf(w, v4.y, a1);
            a2 = fmaf(w, v4.z, a2);
            a3 = fmaf(w, v4.w, a3);
        }
        reinterpret_cast<float4*>(&acc_s[warp][lane * 4])[0] = make_float4(a0, a1, a2, a3);
        if (lane == 0) l_s[warp] = l;
        __syncthreads();

        // ---- combine warps, normalize, update u ----
        if (tid < D_) {
            float lt = 1e-5f;
            #pragma unroll
            for (int w = 0; w < NWARP; w++) lt += l_s[w];
            float oa = 0.f;
            #pragma unroll
            for (int w = 0; w < NWARP; w++) oa += acc_s[w][tid];
            u_s[tid] = ub_s[tid] + oa / lt;
        }
        __syncthreads();
    }

    if (tid < D_) out[b * D_ + tid] = u_s[tid];
}

extern "C" void kernel_launch(void* const* d_in, const int* in_sizes, int n_in,
                              void* d_out, int out_size)
{
    // metadata order: 0 e1_embeded, 1 rel_embeded(unused), 2 nei_embeded_key(unused),
    // 3 nei_embeded_value, 4 nei_mask, 5 linfc_w, 6 linfc_b, 7 attfc_w, 8 attfc_b, 9 dim(unused)
    const float* e1    = (const float*)d_in[0];
    const float* value = (const float*)d_in[3];
    const float* nmask = (const float*)d_in[4];
    const float* linw  = (const float*)d_in[5];
    const float* linb  = (const float*)d_in[6];
    const float* attw  = (const float*)d_in[7];
    const float* attb  = (const float*)d_in[8];
    (void)in_sizes; (void)n_in; (void)out_size;

    dmn_encoder_kernel<<<B_, 1024>>>(e1, value, nmask, linw, linb, attw, attb,
                                     (float*)d_out);
}

// round 2
// speedup vs baseline: 1.1934x; 1.1934x over previous
#include <cuda_runtime.h>
#include <cuda_bf16.h>

// DMN_Encoder: 3-hop memory-network, B=128, N=2048, D=128.
// CTA-per-batch persistent kernel.
//  Hop 1: stream fp32 value once; skip masked rows; compute s=v·w_f (hop-
//         invariant, kept in smem), write bf16 copy of v to scratch, and do
//         the hop-1 online-softmax accumulation inline.
//  Hops 2-3: precompute per-row softmax weights w_s[n] from smem s (no
//         shuffles, 32x fewer MUFU slots), then stream the bf16 copy
//         (half the bytes, mostly L2-resident) for o = sum w*v.

#define B_ 128
#define N_ 2048
#define D_ 128
#define NWARP 32
#define RPW (N_ / NWARP)          // 64 rows per warp
#define ROW_U2 (D_ / 4 / 2 * 2)   // 32 uint2 (8B) per bf16 row

__device__ uint2 g_vbf[(size_t)B_ * N_ * ROW_U2];   // 67MB bf16 scratch

__global__ __launch_bounds__(1024, 1)
void dmn_encoder_kernel(const float* __restrict__ e1,
                        const float* __restrict__ value,
                        const float* __restrict__ mask,
                        const float* __restrict__ linw,
                        const float* __restrict__ linb,
                        const float* __restrict__ attw,
                        const float* __restrict__ attb,
                        float* __restrict__ out)
{
    const int b    = blockIdx.x;
    const int tid  = threadIdx.x;
    const int lane = tid & 31;
    const int warp = tid >> 5;

    __shared__ __align__(16) float u_s[D_];
    __shared__ __align__(16) float ub_s[D_];
    __shared__ __align__(16) float acc_s[NWARP][D_];
    __shared__ float l_s[NWARP];
    __shared__ float m_s[N_];     // binary mask
    __shared__ float s_s[N_];     // s[n] = v[n]·w_f  (hop-invariant)
    __shared__ float w_s[N_];     // per-hop softmax numerator weights

    const float4* attw4 = reinterpret_cast<const float4*>(attw);
    const float4 wf4 = attw4[lane];
    const float4 wu4 = attw4[32 + lane];
    const float  b0  = attb[0];

    if (tid < D_) u_s[tid] = e1[b * D_ + tid];
    for (int n = tid; n < N_; n += 1024) m_s[n] = mask[(size_t)b * N_ + n];
    __syncthreads();

    const float* vb = value + (size_t)b * N_ * D_;
    uint2* vbf = g_vbf + (size_t)b * N_ * ROW_U2;

    #pragma unroll 1
    for (int hop = 0; hop < 3; hop++) {
        // ---- cb = u·w_u + b0 (redundant per warp, butterfly) ----
        const float4 u4 = reinterpret_cast<const float4*>(u_s)[lane];
        float cp = u4.x*wu4.x + u4.y*wu4.y + u4.z*wu4.z + u4.w*wu4.w;
        #pragma unroll
        for (int o = 16; o; o >>= 1) cp += __shfl_xor_sync(0xffffffffu, cp, o);
        const float cb    = cp + b0;
        const float sigma = fmaxf(cb, 0.f);      // valid shift: att >= 0

        // ---- u_batch = relu(u @ W^T + bias): warp w -> rows 4w..4w+3 ----
        #pragma unroll
        for (int r = 0; r < 4; r++) {
            const int i = warp * 4 + r;
            const float4 w4 = reinterpret_cast<const float4*>(linw + (size_t)i * D_)[lane];
            float p = w4.x*u4.x + w4.y*u4.y + w4.z*u4.z + w4.w*u4.w;
            #pragma unroll
            for (int o = 16; o; o >>= 1) p += __shfl_xor_sync(0xffffffffu, p, o);
            if (lane == 0) ub_s[i] = fmaxf(p + linb[i], 0.f);
        }

        float a0 = 0.f, a1 = 0.f, a2 = 0.f, a3 = 0.f, l = 0.f;
        const int n0 = warp * RPW;

        if (hop == 0) {
            // ---- hop 1: fp32 stream, compute s, emit bf16 copy ----
            #pragma unroll 4
            for (int k = 0; k < RPW; k++) {
                const int n = n0 + k;
                if (m_s[n] == 0.f) continue;           // warp-uniform skip
                const float4 v4 = reinterpret_cast<const float4*>(vb + (size_t)n * D_)[lane];
                float s = v4.x*wf4.x + v4.y*wf4.y + v4.z*wf4.z + v4.w*wf4.w;
                #pragma unroll
                for (int o = 16; o; o >>= 1) s += __shfl_xor_sync(0xffffffffu, s, o);
                if (lane == 0) s_s[n] = s;
                // bf16 copy (mask==1 here)
                __nv_bfloat162 p0 = __floats2bfloat162_rn(v4.x, v4.y);
                __nv_bfloat162 p1 = __floats2bfloat162_rn(v4.z, v4.w);
                uint2 pk;
                pk.x = *reinterpret_cast<unsigned int*>(&p0);
                pk.y = *reinterpret_cast<unsigned int*>(&p1);
                vbf[(size_t)n * ROW_U2 + lane] = pk;
                // hop-1 accumulation (m==1)
                float att = fmaxf(s + cb, 0.f);
                float w   = __expf(fminf(att - sigma, 80.f));
                l += w;
                a0 = fmaf(w, v4.x, a0);
                a1 = fmaf(w, v4.y, a1);
                a2 = fmaf(w, v4.z, a2);
                a3 = fmaf(w, v4.w, a3);
            }
        } else {
            // ---- phase A: all weights in one sweep (64 warp-exps total) ----
            for (int n = tid; n < N_; n += 1024) {
                float w = 0.f;
                if (m_s[n] != 0.f) {
                    float att = fmaxf(s_s[n] + cb, 0.f);
                    w = __expf(fminf(att - sigma, 80.f));
                }
                w_s[n] = w;
            }
            __syncthreads();
            // ---- phase B: bf16 stream, no shuffles ----
            #pragma unroll 4
            for (int k = 0; k < RPW; k++) {
                const int n = n0 + k;
                const float w = w_s[n];
                if (w == 0.f) continue;                // warp-uniform skip
                uint2 pk = vbf[(size_t)n * ROW_U2 + lane];
                __nv_bfloat162 p0 = *reinterpret_cast<__nv_bfloat162*>(&pk.x);
                __nv_bfloat162 p1 = *reinterpret_cast<__nv_bfloat162*>(&pk.y);
                float2 f0 = __bfloat1622float2(p0);
                float2 f1 = __bfloat1622float2(p1);
                l += w;
                a0 = fmaf(w, f0.x, a0);
                a1 = fmaf(w, f0.y, a1);
                a2 = fmaf(w, f1.x, a2);
                a3 = fmaf(w, f1.y, a3);
            }
        }

        reinterpret_cast<float4*>(&acc_s[warp][lane * 4])[0] = make_float4(a0, a1, a2, a3);
        if (lane == 0) l_s[warp] = l;
        __syncthreads();

        // ---- combine warps, normalize, update u ----
        if (tid < D_) {
            float lt = 1e-5f;
            #pragma unroll
            for (int w = 0; w < NWARP; w++) lt += l_s[w];
            float oa = 0.f;
            #pragma unroll
            for (int w = 0; w < NWARP; w++) oa += acc_s[w][tid];
            u_s[tid] = ub_s[tid] + oa / lt;
        }
        __syncthreads();
    }

    if (tid < D_) out[b * D_ + tid] = u_s[tid];
}

extern "C" void kernel_launch(void* const* d_in, const int* in_sizes, int n_in,
                              void* d_out, int out_size)
{
    // 0 e1, 1 rel(unused), 2 key(unused), 3 value, 4 mask,
    // 5 linfc_w, 6 linfc_b, 7 attfc_w, 8 attfc_b, 9 dim(unused)
    const float* e1    = (const float*)d_in[0];
    const float* value = (const float*)d_in[3];
    const float* nmask = (const float*)d_in[4];
    const float* linw  = (const float*)d_in[5];
    const float* linb  = (const float*)d_in[6];
    const float* attw  = (const float*)d_in[7];
    const float* attb  = (const float*)d_in[8];
    (void)in_sizes; (void)n_in; (void)out_size;

    dmn_encoder_kernel<<<B_, 1024>>>(e1, value, nmask, linw, linb, attw, attb,
                                     (float*)d_out);
}

// round 3
// speedup vs baseline: 1.3763x; 1.1532x over previous
#include <cuda_runtime.h>
#include <cuda_bf16.h>

// DMN_Encoder: 3-hop memory network, B=128, N=2048, D=128.
// CTA-per-batch persistent kernel with ballot-compacted active-row list:
//  - hop 0: dense indexed fp32 stream (branch-free loads -> high MLP),
//           computes hop-invariant s[k], writes COMPACTED bf16 copy.
//  - hops 1-2: per-hop weight sweep (1 exp per active row total), then a
//           contiguous branch-free bf16 stream (unroll 8) over compact rows.

#define B_ 128
#define N_ 2048
#define D_ 128
#define NWARP 32
#define ROW_U2 32                  // 32 uint2 (8B) per bf16 row of 128 elems

__device__ uint2 g_vbf[(size_t)B_ * N_ * ROW_U2];   // 67MB bf16 scratch

__global__ __launch_bounds__(1024, 1)
void dmn_encoder_kernel(const float* __restrict__ e1,
                        const float* __restrict__ value,
                        const float* __restrict__ mask,
                        const float* __restrict__ linw,
                        const float* __restrict__ linb,
                        const float* __restrict__ attw,
                        const float* __restrict__ attb,
                        float* __restrict__ out)
{
    const int b    = blockIdx.x;
    const int tid  = threadIdx.x;
    const int lane = tid & 31;
    const int warp = tid >> 5;

    __shared__ __align__(16) float u_s[D_];
    __shared__ __align__(16) float ub_s[D_];
    __shared__ __align__(16) float acc_s[NWARP][D_];
    __shared__ float l_s[NWARP];
    __shared__ unsigned short tmp_idx[N_];
    __shared__ unsigned short dense_s[N_];
    __shared__ float s_s[N_];     // s[k] compact: v[dense[k]]·w_f
    __shared__ float w_s[N_];     // per-hop softmax numerators, compact
    __shared__ int   cnt_s[NWARP], off_s[NWARP];
    __shared__ int   total_s;

    const float4* attw4 = reinterpret_cast<const float4*>(attw);
    const float4 wf4 = attw4[lane];
    const float4 wu4 = attw4[32 + lane];
    const float  b0  = attb[0];

    const float* vb = value + (size_t)b * N_ * D_;
    const float* mb = mask  + (size_t)b * N_;
    uint2*       vbf = g_vbf + (size_t)b * N_ * ROW_U2;

    if (tid < D_) u_s[tid] = e1[b * D_ + tid];

    // ---- one-time ballot compaction of active rows ----
    {
        const int base = warp * 64;
        const float m0 = mb[base + lane];
        const float m1 = mb[base + 32 + lane];
        const unsigned bal0 = __ballot_sync(0xffffffffu, m0 != 0.f);
        const unsigned bal1 = __ballot_sync(0xffffffffu, m1 != 0.f);
        const int cnt0 = __popc(bal0);
        if (m0 != 0.f)
            tmp_idx[base + __popc(bal0 & ((1u << lane) - 1u))]
                = (unsigned short)(base + lane);
        if (m1 != 0.f)
            tmp_idx[base + cnt0 + __popc(bal1 & ((1u << lane) - 1u))]
                = (unsigned short)(base + 32 + lane);
        if (lane == 0) cnt_s[warp] = cnt0 + __popc(bal1);
    }
    __syncthreads();
    if (warp == 0) {
        int c = cnt_s[lane], x = c;
        #pragma unroll
        for (int o = 1; o < 32; o <<= 1) {
            int y = __shfl_up_sync(0xffffffffu, x, o);
            if (lane >= o) x += y;
        }
        off_s[lane] = x - c;
        if (lane == 31) total_s = x;
    }
    __syncthreads();
    {
        const int off = off_s[warp], cnt = cnt_s[warp];
        for (int j = lane; j < cnt; j += 32)
            dense_s[off + j] = tmp_idx[warp * 64 + j];
    }
    __syncthreads();

    const int total = total_s;
    const int kb = (total * warp) >> 5;
    const int ke = (total * (warp + 1)) >> 5;

    #pragma unroll 1
    for (int hop = 0; hop < 3; hop++) {
        // ---- cb = u·w_u + b0 ----
        const float4 u4 = reinterpret_cast<const float4*>(u_s)[lane];
        float cp = u4.x*wu4.x + u4.y*wu4.y + u4.z*wu4.z + u4.w*wu4.w;
        #pragma unroll
        for (int o = 16; o; o >>= 1) cp += __shfl_xor_sync(0xffffffffu, cp, o);
        const float cb    = cp + b0;
        const float sigma = fmaxf(cb, 0.f);     // valid shift: att >= 0

        // ---- u_batch = relu(u @ W^T + b): warp w -> rows 4w..4w+3 ----
        #pragma unroll
        for (int r = 0; r < 4; r++) {
            const int i = warp * 4 + r;
            const float4 w4 = reinterpret_cast<const float4*>(linw + (size_t)i * D_)[lane];
            float p = w4.x*u4.x + w4.y*u4.y + w4.z*u4.z + w4.w*u4.w;
            #pragma unroll
            for (int o = 16; o; o >>= 1) p += __shfl_xor_sync(0xffffffffu, p, o);
            if (lane == 0) ub_s[i] = fmaxf(p + linb[i], 0.f);
        }

        float a0 = 0.f, a1 = 0.f, a2 = 0.f, a3 = 0.f, l = 0.f;

        if (hop == 0) {
            // ---- dense indexed fp32 stream ----
            #pragma unroll 4
            for (int k = kb; k < ke; k++) {
                const int n = dense_s[k];
                const float4 v4 = reinterpret_cast<const float4*>(vb + (size_t)n * D_)[lane];
                float s = v4.x*wf4.x + v4.y*wf4.y + v4.z*wf4.z + v4.w*wf4.w;
                #pragma unroll
                for (int o = 16; o; o >>= 1) s += __shfl_xor_sync(0xffffffffu, s, o);
                if (lane == 0) s_s[k] = s;
                __nv_bfloat162 p0 = __floats2bfloat162_rn(v4.x, v4.y);
                __nv_bfloat162 p1 = __floats2bfloat162_rn(v4.z, v4.w);
                uint2 pk;
                pk.x = *reinterpret_cast<unsigned int*>(&p0);
                pk.y = *reinterpret_cast<unsigned int*>(&p1);
                vbf[(size_t)k * ROW_U2 + lane] = pk;     // compacted row k
                const float att = fmaxf(s + cb, 0.f);
                const float w   = __expf(fminf(att - sigma, 80.f));
                l += w;
                a0 = fmaf(w, v4.x, a0);
                a1 = fmaf(w, v4.y, a1);
                a2 = fmaf(w, v4.z, a2);
                a3 = fmaf(w, v4.w, a3);
            }
        } else {
            // ---- phase A: weight sweep (one exp per active row) ----
            for (int k = tid; k < total; k += 1024) {
                const float att = fmaxf(s_s[k] + cb, 0.f);
                w_s[k] = __expf(fminf(att - sigma, 80.f));
            }
            __syncthreads();
            // ---- phase B: contiguous branch-free bf16 stream ----
            #pragma unroll 8
            for (int k = kb; k < ke; k++) {
                const float w = w_s[k];
                const uint2 pk = vbf[(size_t)k * ROW_U2 + lane];
                const __nv_bfloat162 p0 = *reinterpret_cast<const __nv_bfloat162*>(&pk.x);
                const __nv_bfloat162 p1 = *reinterpret_cast<const __nv_bfloat162*>(&pk.y);
                const float2 f0 = __bfloat1622float2(p0);
                const float2 f1 = __bfloat1622float2(p1);
                l += w;
                a0 = fmaf(w, f0.x, a0);
                a1 = fmaf(w, f0.y, a1);
                a2 = fmaf(w, f1.x, a2);
                a3 = fmaf(w, f1.y, a3);
            }
        }

        reinterpret_cast<float4*>(&acc_s[warp][lane * 4])[0] = make_float4(a0, a1, a2, a3);
        if (lane == 0) l_s[warp] = l;
        __syncthreads();

        if (tid < D_) {
            float lt = 1e-5f;
            #pragma unroll
            for (int w = 0; w < NWARP; w++) lt += l_s[w];
            float oa = 0.f;
            #pragma unroll
            for (int w = 0; w < NWARP; w++) oa += acc_s[w][tid];
            u_s[tid] = ub_s[tid] + oa / lt;
        }
        __syncthreads();
    }

    if (tid < D_) out[b * D_ + tid] = u_s[tid];
}

extern "C" void kernel_launch(void* const* d_in, const int* in_sizes, int n_in,
                              void* d_out, int out_size)
{
    // 0 e1, 1 rel(unused), 2 key(unused), 3 value, 4 mask,
    // 5 linfc_w, 6 linfc_b, 7 attfc_w, 8 attfc_b, 9 dim(unused)
    const float* e1    = (const float*)d_in[0];
    const float* value = (const float*)d_in[3];
    const float* nmask = (const float*)d_in[4];
    const float* linw  = (const float*)d_in[5];
    const float* linb  = (const float*)d_in[6];
    const float* attw  = (const float*)d_in[7];
    const float* attb  = (const float*)d_in[8];
    (void)in_sizes; (void)n_in; (void)out_size;

    dmn_encoder_kernel<<<B_, 1024>>>(e1, value, nmask, linw, linb, attw, attb,
                                     (float*)d_out);
}